// round 13
// baseline (speedup 1.0000x reference)
#include <cuda_runtime.h>
#include <cuda_bf16.h>
#include <stdint.h>

#define NN   100000
#define DIM  128
#define EE   640000

// Scratch (device globals — allocation-free rule). Referenced ONLY in device code.
__device__ float d_g[(size_t)NN * DIM];    // g = (h @ W) * dinv[row]
__device__ float d_agg[(size_t)NN * DIM];  // aggregation (init = g => self loop)
__device__ float d_h[(size_t)NN * DIM];    // hidden activations (fp32)
__device__ int   d_deg[NN];
__device__ float d_dinv[NN];

// ---------------------------------------------------------------------------
// degree / norm
// ---------------------------------------------------------------------------
__global__ void k_init_deg() {
    int i = blockIdx.x * blockDim.x + threadIdx.x;
    if (i < NN) d_deg[i] = 1;  // self loop
}
__global__ void k_count_deg(const int* __restrict__ dst) {
    int i = blockIdx.x * blockDim.x + threadIdx.x;
    if (i < EE) atomicAdd(&d_deg[dst[i]], 1);
}
__global__ void k_dinv() {
    int i = blockIdx.x * blockDim.x + threadIdx.x;
    if (i < NN) d_dinv[i] = rsqrtf((float)d_deg[i]);
}

// ---------------------------------------------------------------------------
// GEMM: g[r,:] = (in[r,:] @ W) * dinv[r]; also agg = g (self-loop term).
// 32 rows x 128 cols per block, 256 threads; fp32 FFMA core, float4 smem fills.
// use_internal: read layer input from device-global d_h (NEVER pass the symbol
// from host — host shadow is ATS-readable garbage/zeros on GB300).
// ---------------------------------------------------------------------------
__global__ void k_gemm_scale(const float* __restrict__ in_ext,
                             const float* __restrict__ W,
                             int use_internal) {
    __shared__ float xs[32][132];   // padded (132: float4-aligned, conflict-free)
    __shared__ float ws[32][128];

    const float* __restrict__ in = use_internal ? d_h : in_ext;

    const int tid  = threadIdx.x;
    const int lane = tid & 31;
    const int warp = tid >> 5;
    const int row0 = blockIdx.x * 32;
    const int c0   = warp * 16;

    float4 acc0 = {0,0,0,0}, acc1 = {0,0,0,0}, acc2 = {0,0,0,0}, acc3 = {0,0,0,0};

    const int xr  = tid >> 3;        // 0..31 (row within tile)
    const int xc4 = tid & 7;         // 0..7  (float4 within 32-col chunk)
    const int wr4 = tid & 31;        // float4 within 128-col row
    const int wk0 = tid >> 5;        // base k (stride 8)

    for (int kk = 0; kk < DIM; kk += 32) {
        // x chunk: 32 rows x 32 k, one float4 per thread
        {
            int gr = row0 + xr;
            float4 v = (gr < NN)
                ? *(const float4*)(in + (size_t)gr * DIM + kk + xc4 * 4)
                : make_float4(0.f, 0.f, 0.f, 0.f);
            *(float4*)&xs[xr][xc4 * 4] = v;
        }
        // W chunk: 32 k x 128 cols, four float4 per thread
        #pragma unroll
        for (int i = 0; i < 4; i++) {
            int k = wk0 + i * 8;
            *(float4*)&ws[k][wr4 * 4] =
                *(const float4*)(W + (size_t)(kk + k) * DIM + wr4 * 4);
        }
        __syncthreads();

        #pragma unroll
        for (int k = 0; k < 32; k++) {
            float a = xs[lane][k];
            const float4* wp = (const float4*)&ws[k][c0];
            float4 w0 = wp[0], w1 = wp[1], w2 = wp[2], w3 = wp[3];
            acc0.x += a * w0.x; acc0.y += a * w0.y; acc0.z += a * w0.z; acc0.w += a * w0.w;
            acc1.x += a * w1.x; acc1.y += a * w1.y; acc1.z += a * w1.z; acc1.w += a * w1.w;
            acc2.x += a * w2.x; acc2.y += a * w2.y; acc2.z += a * w2.z; acc2.w += a * w2.w;
            acc3.x += a * w3.x; acc3.y += a * w3.y; acc3.z += a * w3.z; acc3.w += a * w3.w;
        }
        __syncthreads();
    }

    int gr = row0 + lane;
    if (gr < NN) {
        float dv = d_dinv[gr];
        acc0.x *= dv; acc0.y *= dv; acc0.z *= dv; acc0.w *= dv;
        acc1.x *= dv; acc1.y *= dv; acc1.z *= dv; acc1.w *= dv;
        acc2.x *= dv; acc2.y *= dv; acc2.z *= dv; acc2.w *= dv;
        acc3.x *= dv; acc3.y *= dv; acc3.z *= dv; acc3.w *= dv;
        float4* gp = (float4*)(d_g   + (size_t)gr * DIM + c0);
        float4* ap = (float4*)(d_agg + (size_t)gr * DIM + c0);
        gp[0] = acc0; gp[1] = acc1; gp[2] = acc2; gp[3] = acc3;
        ap[0] = acc0; ap[1] = acc1; ap[2] = acc2; ap[3] = acc3;
    }
}

// ---------------------------------------------------------------------------
// Edge scatter: agg[dst] += g[src]  (one warp per edge; scalar RED.ADD.F32)
// ---------------------------------------------------------------------------
__global__ void k_scatter(const int* __restrict__ src,
                          const int* __restrict__ dst) {
    int gw   = (blockIdx.x * blockDim.x + threadIdx.x) >> 5;
    int lane = threadIdx.x & 31;
    if (gw >= EE) return;
    int s = __ldg(&src[gw]);
    int d = __ldg(&dst[gw]);
    float4 v = ((const float4*)(d_g + (size_t)s * DIM))[lane];
    float* ap = d_agg + (size_t)d * DIM + lane * 4;
    atomicAdd(ap + 0, v.x);
    atomicAdd(ap + 1, v.y);
    atomicAdd(ap + 2, v.z);
    atomicAdd(ap + 3, v.w);
}

// ---------------------------------------------------------------------------
// Epilogue: h = relu(agg * dinv[row] + b)
// ---------------------------------------------------------------------------
__global__ void k_epilogue(const float* __restrict__ b) {
    int idx = blockIdx.x * blockDim.x + threadIdx.x;   // NN*32 float4 chunks
    if (idx >= NN * 32) return;
    int row = idx >> 5;
    int c4  = idx & 31;
    float dv = d_dinv[row];
    float4 v  = ((const float4*)d_agg)[idx];
    float4 bb = ((const float4*)b)[c4];
    v.x = fmaxf(fmaf(v.x, dv, bb.x), 0.0f);
    v.y = fmaxf(fmaf(v.y, dv, bb.y), 0.0f);
    v.z = fmaxf(fmaf(v.z, dv, bb.z), 0.0f);
    v.w = fmaxf(fmaf(v.w, dv, bb.w), 0.0f);
    ((float4*)d_h)[idx] = v;
}

// ---------------------------------------------------------------------------
// Fused layer-2 epilogue + FC head: out[r,:] = relu(agg*dinv + b2) @ Wfc + bfc
// One warp per row.
// ---------------------------------------------------------------------------
__global__ void k_fc(const float* __restrict__ b2,
                     const float* __restrict__ Wfc,
                     const float* __restrict__ bfc,
                     float* __restrict__ out) {
    int gw   = (blockIdx.x * blockDim.x + threadIdx.x) >> 5;
    int lane = threadIdx.x & 31;
    if (gw >= NN) return;
    float dv = d_dinv[gw];
    float4 v  = ((const float4*)(d_agg + (size_t)gw * DIM))[lane];
    float4 bb = ((const float4*)b2)[lane];
    float h0 = fmaxf(fmaf(v.x, dv, bb.x), 0.0f);
    float h1 = fmaxf(fmaf(v.y, dv, bb.y), 0.0f);
    float h2 = fmaxf(fmaf(v.z, dv, bb.z), 0.0f);
    float h3 = fmaxf(fmaf(v.w, dv, bb.w), 0.0f);
    int k0 = lane * 4;
    float4 wa = *(const float4*)(Wfc + (k0 + 0) * 2);   // rows k0,k0+1 (c0,c1 pairs)
    float4 wb = *(const float4*)(Wfc + (k0 + 2) * 2);   // rows k0+2,k0+3
    float c0 = h0 * wa.x + h1 * wa.z + h2 * wb.x + h3 * wb.z;
    float c1 = h0 * wa.y + h1 * wa.w + h2 * wb.y + h3 * wb.w;
    #pragma unroll
    for (int off = 16; off > 0; off >>= 1) {
        c0 += __shfl_down_sync(0xFFFFFFFFu, c0, off);
        c1 += __shfl_down_sync(0xFFFFFFFFu, c1, off);
    }
    if (lane == 0) {
        out[(size_t)gw * 2 + 0] = c0 + bfc[0];
        out[(size_t)gw * 2 + 1] = c1 + bfc[1];
    }
}

// ---------------------------------------------------------------------------
// launch — positional binding (confirmed by R10 diagnostics: dict order,
// fp32 tensors, int32 edge_index laid out [2, E] contiguous)
// ---------------------------------------------------------------------------
extern "C" void kernel_launch(void* const* d_in, const int* in_sizes, int n_in,
                              void* d_out, int out_size) {
    const float* x   = (const float*)d_in[0];
    const int*   ei  = (const int*)  d_in[1];
    const float* W1  = (const float*)d_in[2];
    const float* b1  = (const float*)d_in[3];
    const float* W2  = (const float*)d_in[4];
    const float* b2  = (const float*)d_in[5];
    const float* Wfc = (const float*)d_in[6];
    const float* bfc = (const float*)d_in[7];
    float* out = (float*)d_out;

    const int* src = ei;
    const int* dst = ei + EE;

    const int T = 256;
    const int gemm_blocks    = (NN + 31) / 32;
    const int scatter_blocks = ((EE * 32) + T - 1) / T;
    const int epi_blocks     = ((NN * 32) + T - 1) / T;

    k_init_deg<<<(NN + T - 1) / T, T>>>();
    k_count_deg<<<(EE + T - 1) / T, T>>>(dst);
    k_dinv<<<(NN + T - 1) / T, T>>>();

    // layer 1 (input: external x)
    k_gemm_scale<<<gemm_blocks, T>>>(x, W1, 0);
    k_scatter<<<scatter_blocks, T>>>(src, dst);
    k_epilogue<<<epi_blocks, T>>>(b1);

    // layer 2 (input: internal d_h — selected INSIDE the kernel) + head
    k_gemm_scale<<<gemm_blocks, T>>>(nullptr, W2, 1);
    k_scatter<<<scatter_blocks, T>>>(src, dst);
    k_fc<<<epi_blocks, T>>>(b2, Wfc, bfc, out);
}

// round 14
// speedup vs baseline: 1.5519x; 1.5519x over previous
#include <cuda_runtime.h>
#include <cuda_bf16.h>
#include <stdint.h>

#define NN   100000
#define DIM  128
#define EE   640000
#define BM   128     // GEMM tile rows

// Scratch (device globals — allocation-free rule). Referenced ONLY in device code.
__device__ float d_g[(size_t)NN * DIM];    // g = (h @ W) * dinv[row]
__device__ float d_agg[(size_t)NN * DIM];  // aggregation (init = g => self loop)
__device__ float d_h[(size_t)NN * DIM];    // hidden activations (fp32)
__device__ int   d_deg[NN];
__device__ float d_dinv[NN];

// ---------------------------------------------------------------------------
// degree / norm
// ---------------------------------------------------------------------------
__global__ void k_init_deg() {
    int i = blockIdx.x * blockDim.x + threadIdx.x;
    if (i < NN) d_deg[i] = 1;  // self loop
}
__global__ void k_count_deg(const int* __restrict__ dst) {
    int i = blockIdx.x * blockDim.x + threadIdx.x;
    if (i < EE) atomicAdd(&d_deg[dst[i]], 1);
}
__global__ void k_dinv() {
    int i = blockIdx.x * blockDim.x + threadIdx.x;
    if (i < NN) d_dinv[i] = rsqrtf((float)d_deg[i]);
}

// ---------------------------------------------------------------------------
// GEMM: g[r,:] = (in[r,:] @ W) * dinv[r]; also agg = g (self-loop term).
// 128x128 tile, 256 threads, register blocking 4 rows x 16 cols per thread.
// xs stored K-MAJOR (xs[k][row], +4 pad) so per-k row reads are conflict-free;
// ws reads are warp-broadcast (free). ~0.3 smem B/FMA -> fma-pipe-bound.
// ---------------------------------------------------------------------------
__global__ void __launch_bounds__(256, 2)
k_gemm_scale(const float* __restrict__ in_ext,
             const float* __restrict__ W,
             int use_internal) {
    __shared__ float xs[32][BM + 4];   // k-major; bank stride 4 => lanes distinct
    __shared__ float ws[32][DIM];

    const float* __restrict__ in = use_internal ? d_h : in_ext;

    const int tid  = threadIdx.x;
    const int lane = tid & 31;
    const int warp = tid >> 5;
    const int row0 = blockIdx.x * BM;
    const int c0   = warp * 16;

    float4 acc[4][4];
    #pragma unroll
    for (int i = 0; i < 4; i++)
        #pragma unroll
        for (int j = 0; j < 4; j++)
            acc[i][j] = make_float4(0.f, 0.f, 0.f, 0.f);

    // x-load mapping: 128 rows x 32 k per chunk; 2 threads per row, 4 float4 each
    const int xrow = tid & 127;        // 0..127
    const int xkq  = (tid >> 7) * 4;   // float4 slot 0 or 4 (k offset 0/16)
    // W-load mapping: thread -> (k = warp + 8i, float4 col = lane)
    const int wr4  = lane;

    for (int kk = 0; kk < DIM; kk += 32) {
        {   // x chunk (transposed store: gmem row-major -> smem k-major)
            int gr = row0 + xrow;
            const float4* xp = (const float4*)(in + (size_t)gr * DIM + kk) + xkq;
            #pragma unroll
            for (int j = 0; j < 4; j++) {
                float4 v = (gr < NN) ? xp[j] : make_float4(0.f, 0.f, 0.f, 0.f);
                int kb = (xkq + j) * 4;
                xs[kb + 0][xrow] = v.x;
                xs[kb + 1][xrow] = v.y;
                xs[kb + 2][xrow] = v.z;
                xs[kb + 3][xrow] = v.w;
            }
        }
        #pragma unroll
        for (int i = 0; i < 4; i++) {   // W chunk: 32 k x 128 cols
            int k = warp + i * 8;
            *(float4*)&ws[k][wr4 * 4] =
                *(const float4*)(W + (size_t)(kk + k) * DIM + wr4 * 4);
        }
        __syncthreads();

        #pragma unroll
        for (int k = 0; k < 32; k++) {
            float a0 = xs[k][lane];
            float a1 = xs[k][lane + 32];
            float a2 = xs[k][lane + 64];
            float a3 = xs[k][lane + 96];
            const float4* wp = (const float4*)&ws[k][c0];
            float4 w0 = wp[0], w1 = wp[1], w2 = wp[2], w3 = wp[3];
            acc[0][0].x += a0*w0.x; acc[0][0].y += a0*w0.y; acc[0][0].z += a0*w0.z; acc[0][0].w += a0*w0.w;
            acc[0][1].x += a0*w1.x; acc[0][1].y += a0*w1.y; acc[0][1].z += a0*w1.z; acc[0][1].w += a0*w1.w;
            acc[0][2].x += a0*w2.x; acc[0][2].y += a0*w2.y; acc[0][2].z += a0*w2.z; acc[0][2].w += a0*w2.w;
            acc[0][3].x += a0*w3.x; acc[0][3].y += a0*w3.y; acc[0][3].z += a0*w3.z; acc[0][3].w += a0*w3.w;
            acc[1][0].x += a1*w0.x; acc[1][0].y += a1*w0.y; acc[1][0].z += a1*w0.z; acc[1][0].w += a1*w0.w;
            acc[1][1].x += a1*w1.x; acc[1][1].y += a1*w1.y; acc[1][1].z += a1*w1.z; acc[1][1].w += a1*w1.w;
            acc[1][2].x += a1*w2.x; acc[1][2].y += a1*w2.y; acc[1][2].z += a1*w2.z; acc[1][2].w += a1*w2.w;
            acc[1][3].x += a1*w3.x; acc[1][3].y += a1*w3.y; acc[1][3].z += a1*w3.z; acc[1][3].w += a1*w3.w;
            acc[2][0].x += a2*w0.x; acc[2][0].y += a2*w0.y; acc[2][0].z += a2*w0.z; acc[2][0].w += a2*w0.w;
            acc[2][1].x += a2*w1.x; acc[2][1].y += a2*w1.y; acc[2][1].z += a2*w1.z; acc[2][1].w += a2*w1.w;
            acc[2][2].x += a2*w2.x; acc[2][2].y += a2*w2.y; acc[2][2].z += a2*w2.z; acc[2][2].w += a2*w2.w;
            acc[2][3].x += a2*w3.x; acc[2][3].y += a2*w3.y; acc[2][3].z += a2*w3.z; acc[2][3].w += a2*w3.w;
            acc[3][0].x += a3*w0.x; acc[3][0].y += a3*w0.y; acc[3][0].z += a3*w0.z; acc[3][0].w += a3*w0.w;
            acc[3][1].x += a3*w1.x; acc[3][1].y += a3*w1.y; acc[3][1].z += a3*w1.z; acc[3][1].w += a3*w1.w;
            acc[3][2].x += a3*w2.x; acc[3][2].y += a3*w2.y; acc[3][2].z += a3*w2.z; acc[3][2].w += a3*w2.w;
            acc[3][3].x += a3*w3.x; acc[3][3].y += a3*w3.y; acc[3][3].z += a3*w3.z; acc[3][3].w += a3*w3.w;
        }
        __syncthreads();
    }

    #pragma unroll
    for (int i = 0; i < 4; i++) {
        int gr = row0 + lane + 32 * i;
        if (gr < NN) {
            float dv = d_dinv[gr];
            float4* gp = (float4*)(d_g   + (size_t)gr * DIM + c0);
            float4* ap = (float4*)(d_agg + (size_t)gr * DIM + c0);
            #pragma unroll
            for (int j = 0; j < 4; j++) {
                float4 v = acc[i][j];
                v.x *= dv; v.y *= dv; v.z *= dv; v.w *= dv;
                gp[j] = v;
                ap[j] = v;
            }
        }
    }
}

// ---------------------------------------------------------------------------
// Edge scatter: agg[dst] += g[src]  (warp/edge; ONE red.v4 per lane = 4x fewer
// LTS atomic ops than scalar atomicAdd)
// ---------------------------------------------------------------------------
__global__ void k_scatter(const int* __restrict__ src,
                          const int* __restrict__ dst) {
    int gw   = (blockIdx.x * blockDim.x + threadIdx.x) >> 5;
    int lane = threadIdx.x & 31;
    if (gw >= EE) return;
    int s = __ldg(&src[gw]);
    int d = __ldg(&dst[gw]);
    float4 v = ((const float4*)(d_g + (size_t)s * DIM))[lane];
    float* ap = d_agg + (size_t)d * DIM + lane * 4;
    asm volatile("red.global.add.v4.f32 [%0], {%1, %2, %3, %4};"
                 :: "l"(ap), "f"(v.x), "f"(v.y), "f"(v.z), "f"(v.w)
                 : "memory");
}

// ---------------------------------------------------------------------------
// Epilogue: h = relu(agg * dinv[row] + b)
// ---------------------------------------------------------------------------
__global__ void k_epilogue(const float* __restrict__ b) {
    int idx = blockIdx.x * blockDim.x + threadIdx.x;   // NN*32 float4 chunks
    if (idx >= NN * 32) return;
    int row = idx >> 5;
    int c4  = idx & 31;
    float dv = d_dinv[row];
    float4 v  = ((const float4*)d_agg)[idx];
    float4 bb = ((const float4*)b)[c4];
    v.x = fmaxf(fmaf(v.x, dv, bb.x), 0.0f);
    v.y = fmaxf(fmaf(v.y, dv, bb.y), 0.0f);
    v.z = fmaxf(fmaf(v.z, dv, bb.z), 0.0f);
    v.w = fmaxf(fmaf(v.w, dv, bb.w), 0.0f);
    ((float4*)d_h)[idx] = v;
}

// ---------------------------------------------------------------------------
// Fused layer-2 epilogue + FC head: out[r,:] = relu(agg*dinv + b2) @ Wfc + bfc
// ---------------------------------------------------------------------------
__global__ void k_fc(const float* __restrict__ b2,
                     const float* __restrict__ Wfc,
                     const float* __restrict__ bfc,
                     float* __restrict__ out) {
    int gw   = (blockIdx.x * blockDim.x + threadIdx.x) >> 5;
    int lane = threadIdx.x & 31;
    if (gw >= NN) return;
    float dv = d_dinv[gw];
    float4 v  = ((const float4*)(d_agg + (size_t)gw * DIM))[lane];
    float4 bb = ((const float4*)b2)[lane];
    float h0 = fmaxf(fmaf(v.x, dv, bb.x), 0.0f);
    float h1 = fmaxf(fmaf(v.y, dv, bb.y), 0.0f);
    float h2 = fmaxf(fmaf(v.z, dv, bb.z), 0.0f);
    float h3 = fmaxf(fmaf(v.w, dv, bb.w), 0.0f);
    int k0 = lane * 4;
    float4 wa = *(const float4*)(Wfc + (k0 + 0) * 2);
    float4 wb = *(const float4*)(Wfc + (k0 + 2) * 2);
    float c0 = h0 * wa.x + h1 * wa.z + h2 * wb.x + h3 * wb.z;
    float c1 = h0 * wa.y + h1 * wa.w + h2 * wb.y + h3 * wb.w;
    #pragma unroll
    for (int off = 16; off > 0; off >>= 1) {
        c0 += __shfl_down_sync(0xFFFFFFFFu, c0, off);
        c1 += __shfl_down_sync(0xFFFFFFFFu, c1, off);
    }
    if (lane == 0) {
        out[(size_t)gw * 2 + 0] = c0 + bfc[0];
        out[(size_t)gw * 2 + 1] = c1 + bfc[1];
    }
}

// ---------------------------------------------------------------------------
// launch
// ---------------------------------------------------------------------------
extern "C" void kernel_launch(void* const* d_in, const int* in_sizes, int n_in,
                              void* d_out, int out_size) {
    const float* x   = (const float*)d_in[0];
    const int*   ei  = (const int*)  d_in[1];
    const float* W1  = (const float*)d_in[2];
    const float* b1  = (const float*)d_in[3];
    const float* W2  = (const float*)d_in[4];
    const float* b2  = (const float*)d_in[5];
    const float* Wfc = (const float*)d_in[6];
    const float* bfc = (const float*)d_in[7];
    float* out = (float*)d_out;

    const int* src = ei;
    const int* dst = ei + EE;

    const int T = 256;
    const int gemm_blocks    = (NN + BM - 1) / BM;
    const int scatter_blocks = ((EE * 32) + T - 1) / T;
    const int epi_blocks     = ((NN * 32) + T - 1) / T;

    k_init_deg<<<(NN + T - 1) / T, T>>>();
    k_count_deg<<<(EE + T - 1) / T, T>>>(dst);
    k_dinv<<<(NN + T - 1) / T, T>>>();

    // layer 1 (input: external x)
    k_gemm_scale<<<gemm_blocks, T>>>(x, W1, 0);
    k_scatter<<<scatter_blocks, T>>>(src, dst);
    k_epilogue<<<epi_blocks, T>>>(b1);

    // layer 2 (input: internal d_h — selected INSIDE the kernel) + head
    k_gemm_scale<<<gemm_blocks, T>>>(nullptr, W2, 1);
    k_scatter<<<scatter_blocks, T>>>(src, dst);
    k_fc<<<epi_blocks, T>>>(b2, Wfc, bfc, out);
}

// round 17
// speedup vs baseline: 1.6111x; 1.0382x over previous
#include <cuda_runtime.h>
#include <cuda_bf16.h>
#include <stdint.h>

#define NN   100000
#define DIM  128
#define EE   640000
#define BM   128     // GEMM tile rows

// Scratch (device globals — allocation-free rule). Referenced ONLY in device code.
__device__ float d_g[(size_t)NN * DIM];    // g = (h @ W) * dinv[row]
__device__ float d_agg[(size_t)NN * DIM];  // aggregation (init = g => self loop)
__device__ float d_h[(size_t)NN * DIM];    // hidden activations (fp32)
__device__ int   d_deg[NN];
__device__ float d_dinv[NN];

// ---------------------------------------------------------------------------
// degree / norm
// ---------------------------------------------------------------------------
__global__ void k_init_deg() {
    int i = blockIdx.x * blockDim.x + threadIdx.x;
    if (i < NN) d_deg[i] = 1;  // self loop
}
__global__ void k_count_deg(const int* __restrict__ dst) {
    int i = blockIdx.x * blockDim.x + threadIdx.x;
    if (i < EE) atomicAdd(&d_deg[dst[i]], 1);
}
__global__ void k_dinv() {
    int i = blockIdx.x * blockDim.x + threadIdx.x;
    if (i < NN) d_dinv[i] = rsqrtf((float)d_deg[i]);
}

// ---------------------------------------------------------------------------
// Packed fp32x2 helpers (Blackwell base ISA, PTX 8.6 — NOT an 'a' feature)
// ---------------------------------------------------------------------------
__device__ __forceinline__ void ffma2(unsigned long long& acc,
                                      unsigned long long a2,
                                      unsigned long long b2) {
    asm("fma.rn.f32x2 %0, %1, %2, %0;" : "+l"(acc) : "l"(a2), "l"(b2));
}
__device__ __forceinline__ unsigned long long pack2(float a) {
    unsigned long long r;
    asm("mov.b64 %0, {%1, %1};" : "=l"(r) : "f"(a));
    return r;
}
__device__ __forceinline__ float2 unpack2(unsigned long long v) {
    float2 r;
    asm("mov.b64 {%0, %1}, %2;" : "=f"(r.x), "=f"(r.y) : "l"(v));
    return r;
}

// ---------------------------------------------------------------------------
// GEMM: g[r,:] = (in[r,:] @ W) * dinv[r]; also agg = g (self-loop term).
// 128x128 tile, 256 threads, register blocking 4 rows x 16 cols per thread.
// Inner math uses fma.rn.f32x2: 32 packed FMAs per k-step per thread
// (half the issue slots of scalar FFMA -> fma-pipe-bound at 2x rate).
// xs K-major (conflict-free per-k row reads); ws reads warp-broadcast.
// ---------------------------------------------------------------------------
__global__ void __launch_bounds__(256, 2)
k_gemm_scale(const float* __restrict__ in_ext,
             const float* __restrict__ W,
             int use_internal) {
    __shared__ float xs[32][BM + 4];   // k-major
    __shared__ float ws[32][DIM];

    const float* __restrict__ in = use_internal ? d_h : in_ext;

    const int tid  = threadIdx.x;
    const int lane = tid & 31;
    const int warp = tid >> 5;
    const int row0 = blockIdx.x * BM;
    const int c0   = warp * 16;

    unsigned long long acc[4][8];      // 4 rows x 8 col-pairs (16 cols)
    #pragma unroll
    for (int i = 0; i < 4; i++)
        #pragma unroll
        for (int j = 0; j < 8; j++)
            acc[i][j] = 0ull;          // packed {0.f, 0.f}

    const int xrow = tid & 127;        // 0..127
    const int xkq  = (tid >> 7) * 4;   // float4 slot 0 or 4 (k offset 0/16)
    const int wr4  = lane;

    for (int kk = 0; kk < DIM; kk += 32) {
        {   // x chunk (row-major gmem -> k-major smem)
            int gr = row0 + xrow;
            const float4* xp = (const float4*)(in + (size_t)gr * DIM + kk) + xkq;
            #pragma unroll
            for (int j = 0; j < 4; j++) {
                float4 v = (gr < NN) ? xp[j] : make_float4(0.f, 0.f, 0.f, 0.f);
                int kb = (xkq + j) * 4;
                xs[kb + 0][xrow] = v.x;
                xs[kb + 1][xrow] = v.y;
                xs[kb + 2][xrow] = v.z;
                xs[kb + 3][xrow] = v.w;
            }
        }
        #pragma unroll
        for (int i = 0; i < 4; i++) {   // W chunk: 32 k x 128 cols
            int k = warp + i * 8;
            *(float4*)&ws[k][wr4 * 4] =
                *(const float4*)(W + (size_t)(kk + k) * DIM + wr4 * 4);
        }
        __syncthreads();

        #pragma unroll
        for (int k = 0; k < 32; k++) {
            unsigned long long a0 = pack2(xs[k][lane]);
            unsigned long long a1 = pack2(xs[k][lane + 32]);
            unsigned long long a2 = pack2(xs[k][lane + 64]);
            unsigned long long a3 = pack2(xs[k][lane + 96]);
            // 16 cols = 8 u64 pairs, read as 4x 16B
            const ulonglong2* wp = (const ulonglong2*)&ws[k][c0];
            ulonglong2 wA = wp[0], wB = wp[1], wC = wp[2], wD = wp[3];
            ffma2(acc[0][0], a0, wA.x); ffma2(acc[0][1], a0, wA.y);
            ffma2(acc[0][2], a0, wB.x); ffma2(acc[0][3], a0, wB.y);
            ffma2(acc[0][4], a0, wC.x); ffma2(acc[0][5], a0, wC.y);
            ffma2(acc[0][6], a0, wD.x); ffma2(acc[0][7], a0, wD.y);
            ffma2(acc[1][0], a1, wA.x); ffma2(acc[1][1], a1, wA.y);
            ffma2(acc[1][2], a1, wB.x); ffma2(acc[1][3], a1, wB.y);
            ffma2(acc[1][4], a1, wC.x); ffma2(acc[1][5], a1, wC.y);
            ffma2(acc[1][6], a1, wD.x); ffma2(acc[1][7], a1, wD.y);
            ffma2(acc[2][0], a2, wA.x); ffma2(acc[2][1], a2, wA.y);
            ffma2(acc[2][2], a2, wB.x); ffma2(acc[2][3], a2, wB.y);
            ffma2(acc[2][4], a2, wC.x); ffma2(acc[2][5], a2, wC.y);
            ffma2(acc[2][6], a2, wD.x); ffma2(acc[2][7], a2, wD.y);
            ffma2(acc[3][0], a3, wA.x); ffma2(acc[3][1], a3, wA.y);
            ffma2(acc[3][2], a3, wB.x); ffma2(acc[3][3], a3, wB.y);
            ffma2(acc[3][4], a3, wC.x); ffma2(acc[3][5], a3, wC.y);
            ffma2(acc[3][6], a3, wD.x); ffma2(acc[3][7], a3, wD.y);
        }
        __syncthreads();
    }

    #pragma unroll
    for (int i = 0; i < 4; i++) {
        int gr = row0 + lane + 32 * i;
        if (gr < NN) {
            float dv = d_dinv[gr];
            float4* gp = (float4*)(d_g   + (size_t)gr * DIM + c0);
            float4* ap = (float4*)(d_agg + (size_t)gr * DIM + c0);
            #pragma unroll
            for (int j = 0; j < 4; j++) {
                float2 p0 = unpack2(acc[i][2 * j + 0]);
                float2 p1 = unpack2(acc[i][2 * j + 1]);
                float4 v;
                v.x = p0.x * dv; v.y = p0.y * dv;
                v.z = p1.x * dv; v.w = p1.y * dv;
                gp[j] = v;
                ap[j] = v;
            }
        }
    }
}

// ---------------------------------------------------------------------------
// Edge scatter: agg[dst] += g[src]  (warp/edge; red.v4 per lane)
// ---------------------------------------------------------------------------
__global__ void k_scatter(const int* __restrict__ src,
                          const int* __restrict__ dst) {
    int gw   = (blockIdx.x * blockDim.x + threadIdx.x) >> 5;
    int lane = threadIdx.x & 31;
    if (gw >= EE) return;
    int s = __ldg(&src[gw]);
    int d = __ldg(&dst[gw]);
    float4 v = ((const float4*)(d_g + (size_t)s * DIM))[lane];
    float* ap = d_agg + (size_t)d * DIM + lane * 4;
    asm volatile("red.global.add.v4.f32 [%0], {%1, %2, %3, %4};"
                 :: "l"(ap), "f"(v.x), "f"(v.y), "f"(v.z), "f"(v.w)
                 : "memory");
}

// ---------------------------------------------------------------------------
// Epilogue: h = relu(agg * dinv[row] + b)
// ---------------------------------------------------------------------------
__global__ void k_epilogue(const float* __restrict__ b) {
    int idx = blockIdx.x * blockDim.x + threadIdx.x;   // NN*32 float4 chunks
    if (idx >= NN * 32) return;
    int row = idx >> 5;
    int c4  = idx & 31;
    float dv = d_dinv[row];
    float4 v  = ((const float4*)d_agg)[idx];
    float4 bb = ((const float4*)b)[c4];
    v.x = fmaxf(fmaf(v.x, dv, bb.x), 0.0f);
    v.y = fmaxf(fmaf(v.y, dv, bb.y), 0.0f);
    v.z = fmaxf(fmaf(v.z, dv, bb.z), 0.0f);
    v.w = fmaxf(fmaf(v.w, dv, bb.w), 0.0f);
    ((float4*)d_h)[idx] = v;
}

// ---------------------------------------------------------------------------
// Fused layer-2 epilogue + FC head: out[r,:] = relu(agg*dinv + b2) @ Wfc + bfc
// ---------------------------------------------------------------------------
__global__ void k_fc(const float* __restrict__ b2,
                     const float* __restrict__ Wfc,
                     const float* __restrict__ bfc,
                     float* __restrict__ out) {
    int gw   = (blockIdx.x * blockDim.x + threadIdx.x) >> 5;
    int lane = threadIdx.x & 31;
    if (gw >= NN) return;
    float dv = d_dinv[gw];
    float4 v  = ((const float4*)(d_agg + (size_t)gw * DIM))[lane];
    float4 bb = ((const float4*)b2)[lane];
    float h0 = fmaxf(fmaf(v.x, dv, bb.x), 0.0f);
    float h1 = fmaxf(fmaf(v.y, dv, bb.y), 0.0f);
    float h2 = fmaxf(fmaf(v.z, dv, bb.z), 0.0f);
    float h3 = fmaxf(fmaf(v.w, dv, bb.w), 0.0f);
    int k0 = lane * 4;
    float4 wa = *(const float4*)(Wfc + (k0 + 0) * 2);
    float4 wb = *(const float4*)(Wfc + (k0 + 2) * 2);
    float c0 = h0 * wa.x + h1 * wa.z + h2 * wb.x + h3 * wb.z;
    float c1 = h0 * wa.y + h1 * wa.w + h2 * wb.y + h3 * wb.w;
    #pragma unroll
    for (int off = 16; off > 0; off >>= 1) {
        c0 += __shfl_down_sync(0xFFFFFFFFu, c0, off);
        c1 += __shfl_down_sync(0xFFFFFFFFu, c1, off);
    }
    if (lane == 0) {
        out[(size_t)gw * 2 + 0] = c0 + bfc[0];
        out[(size_t)gw * 2 + 1] = c1 + bfc[1];
    }
}

// ---------------------------------------------------------------------------
// launch
// ---------------------------------------------------------------------------
extern "C" void kernel_launch(void* const* d_in, const int* in_sizes, int n_in,
                              void* d_out, int out_size) {
    const float* x   = (const float*)d_in[0];
    const int*   ei  = (const int*)  d_in[1];
    const float* W1  = (const float*)d_in[2];
    const float* b1  = (const float*)d_in[3];
    const float* W2  = (const float*)d_in[4];
    const float* b2  = (const float*)d_in[5];
    const float* Wfc = (const float*)d_in[6];
    const float* bfc = (const float*)d_in[7];
    float* out = (float*)d_out;

    const int* src = ei;
    const int* dst = ei + EE;

    const int T = 256;
    const int gemm_blocks    = (NN + BM - 1) / BM;
    const int scatter_blocks = ((EE * 32) + T - 1) / T;
    const int epi_blocks     = ((NN * 32) + T - 1) / T;

    k_init_deg<<<(NN + T - 1) / T, T>>>();
    k_count_deg<<<(EE + T - 1) / T, T>>>(dst);
    k_dinv<<<(NN + T - 1) / T, T>>>();

    // layer 1 (input: external x)
    k_gemm_scale<<<gemm_blocks, T>>>(x, W1, 0);
    k_scatter<<<scatter_blocks, T>>>(src, dst);
    k_epilogue<<<epi_blocks, T>>>(b1);

    // layer 2 (input: internal d_h — selected INSIDE the kernel) + head
    k_gemm_scale<<<gemm_blocks, T>>>(nullptr, W2, 1);
    k_scatter<<<scatter_blocks, T>>>(src, dst);
    k_fc<<<epi_blocks, T>>>(b2, Wfc, bfc, out);
}